// round 14
// baseline (speedup 1.0000x reference)
#include <cuda_runtime.h>
#include <cuda_fp16.h>
#include <cstdint>

#define B_  32
#define O_  256
#define KK  49
#define HW  625
#define WO  25
#define CKK 12544

#define THREADS 256          // 8 warps: 4(M) x 2(N), warp tile 32 x 80
#define NGROUP  128          // channel pairs
#define KG      112          // k = ch*56 + ki*8 + kj (kj<7 real)
#define KSTEPS  7
#define PITCH   120
#define PITCHB  240
#define A_TILE  30720        // 128 * 240 (hi only)
#define B_TILE  38400        // 160 * 240

#define XCH     448          // 14 rows * 32 floats per channel
#define XSTG    434          // 14 * 31 staged floats per channel
#define XBUFB   3584

#define SM_A    0            // 2 * 30720
#define SM_B    61440        // 2 * 38400
#define SM_X    138240       // 2 * 3584
#define SM_KM   145408       // 2 * 448 bytes
#define SM_RTAB 146304       // 160 ints
#define SMEM_DYN 147456

// Precomputed fp16 weights (x256), hi only: [t][g][o 128][k 120]
__device__ __half g_W[2][NGROUP][128][PITCH];

__device__ __forceinline__ uint32_t smem_u32(const void* p) {
    uint32_t a;
    asm("{ .reg .u64 t; cvta.to.shared.u64 t, %1; cvt.u32.u64 %0, t; }" : "=r"(a) : "l"(p));
    return a;
}
__device__ __forceinline__ void ldsm4(uint32_t* r, uint32_t addr) {
    asm volatile("ldmatrix.sync.aligned.m8n8.x4.shared.b16 {%0,%1,%2,%3}, [%4];"
                 : "=r"(r[0]), "=r"(r[1]), "=r"(r[2]), "=r"(r[3]) : "r"(addr));
}
// fp16-accumulator MMA, fresh chain (C = 0)
__device__ __forceinline__ void mma_h16z(uint32_t* d, const uint32_t* a, const uint32_t* b) {
    asm volatile("mma.sync.aligned.m16n8k16.row.col.f16.f16.f16.f16 "
                 "{%0,%1}, {%2,%3,%4,%5}, {%6,%7}, {%8,%9};"
                 : "=r"(d[0]), "=r"(d[1])
                 : "r"(a[0]), "r"(a[1]), "r"(a[2]), "r"(a[3]),
                   "r"(b[0]), "r"(b[1]), "r"(0u), "r"(0u));
}
// fp16-accumulator MMA, accumulate into d
__device__ __forceinline__ void mma_h16a(uint32_t* d, const uint32_t* a, const uint32_t* b) {
    asm volatile("mma.sync.aligned.m16n8k16.row.col.f16.f16.f16.f16 "
                 "{%0,%1}, {%2,%3,%4,%5}, {%6,%7}, {%0,%1};"
                 : "+r"(d[0]), "+r"(d[1])
                 : "r"(a[0]), "r"(a[1]), "r"(a[2]), "r"(a[3]),
                   "r"(b[0]), "r"(b[1]));
}
// drain fp16x2 pair into fp32 master accumulators
__device__ __forceinline__ void dq(float* a4, const uint32_t* d) {
    __half2 h0 = *reinterpret_cast<const __half2*>(&d[0]);
    __half2 h1 = *reinterpret_cast<const __half2*>(&d[1]);
    float2 f0 = __half22float2(h0);
    float2 f1 = __half22float2(h1);
    a4[0] += f0.x; a4[1] += f0.y; a4[2] += f1.x; a4[3] += f1.y;
}
#define CP16(dst, src) \
    asm volatile("cp.async.cg.shared.global [%0], [%1], 16;" :: "r"(dst), "l"(src) : "memory")
#define CP_COMMIT() asm volatile("cp.async.commit_group;" ::: "memory")
#define CP_WAIT0()  asm volatile("cp.async.wait_group 0;" ::: "memory")

__global__ void precompute_w(const float* __restrict__ w) {
    long idx = (long)blockIdx.x * 256 + threadIdx.x;   // [t][g][o][k<120]
    int k = idx % PITCH;
    int o = (idx / PITCH) & 127;
    int g = (idx / (PITCH * 128)) & 127;
    int t = (int)(idx / ((long)PITCH * 128 * NGROUP));
    if (t >= 2) return;
    float v = 0.f;
    if (k < KG) {
        int ch = k / 56, r = (k % 56) / 8, kj = k & 7;
        if (kj < 7)
            v = w[(size_t)(t * 128 + o) * CKK + (g * 2 + ch) * KK + r * 7 + kj] * 256.f;
    }
    g_W[t][g][o][k] = __float2half_rn(v);
}

__global__ __launch_bounds__(THREADS)
void dwconv_hmma11(const float* __restrict__ x, const float* __restrict__ kern,
                   const float* __restrict__ bias, float* __restrict__ out)
{
    extern __shared__ __align__(128) char smem[];
    const uint32_t sbase = smem_u32(smem);

    const int tid = threadIdx.x, wid = tid >> 5, lid = tid & 31;
    const int mw = wid >> 1, nw = wid & 1;
    const int blk = blockIdx.x;
    const int pt = blk & 3, t = (blk >> 2) & 1, b = blk >> 3;
    const int p0 = pt * 160, o0 = t * 128;
    const int h0 = p0 / WO;

    int* rtab = (int*)(smem + SM_RTAB);
    if (tid < 160) {
        int pg = p0 + tid;
        rtab[tid] = (pg < HW) ? ((pg / WO) - h0) * 32 + (pg % WO) : -1;
    }

    const float* xb = x    + (size_t)b * 256 * 961;
    const float* kb = kern + (size_t)b * CKK;

    auto kern_fetch = [&](int gg) -> float {
        if (tid >= KG) return 0.f;
        int ch = tid / 56, r = (tid % 56) / 8, kj = tid & 7;
        if (kj >= 7) return 0.f;
        return kb[(size_t)(gg * 2 + ch) * KK + r * 7 + kj];
    };

    auto build_B = [&](int s) {
        char* bt = smem + SM_B + s * B_TILE;
        const float* xs = (const float*)(smem + SM_X + s * XBUFB);
        const float* km = (const float*)(smem + SM_KM + s * 448);
#pragma unroll
        for (int it = 0; it < 9; it++) {
            int wt = it * 8 + wid;        // 70 warp-tasks: 5 p-grp x 2 ch x 7 ki
            if (wt < 70) {
                int pg5 = wt / 14;
                int rem = wt - pg5 * 14;
                int ch = rem / 7, ki = rem - (rem / 7) * 7;
                int p = pg5 * 32 + lid;
                int rb = rtab[p];
                uint4 val = make_uint4(0, 0, 0, 0);
                if (rb >= 0) {
                    const float* kp = km + ch * 56 + ki * 8;
                    const float4 ka = *(const float4*)kp;
                    const float4 kc = *(const float4*)(kp + 4);
                    const float* xp = xs + ch * XCH + rb + ki * 32;
                    __half2 h0v = __floats2half2_rn(xp[0] * ka.x, xp[1] * ka.y);
                    __half2 h1v = __floats2half2_rn(xp[2] * ka.z, xp[3] * ka.w);
                    __half2 h2v = __floats2half2_rn(xp[4] * kc.x, xp[5] * kc.y);
                    __half2 h3v = __floats2half2_rn(xp[6] * kc.z, 0.f);
                    val = make_uint4(*(uint32_t*)&h0v, *(uint32_t*)&h1v,
                                     *(uint32_t*)&h2v, *(uint32_t*)&h3v);
                }
                *(uint4*)(bt + p * PITCHB + (ch * 7 + ki) * 16) = val;
            }
        }
    };
    auto cpasync_A = [&](int gg) {
        const char* src = (const char*)&g_W[t][gg][0][0];
        uint32_t dst = sbase + SM_A + (gg & 1) * A_TILE;
#pragma unroll
        for (int i = 0; i < 8; i++) {
            int idx = i * 256 + tid;
            if (idx < 1920) CP16(dst + idx * 16, src + idx * 16);
        }
        CP_COMMIT();
    };
    auto stage_xk_direct = [&](int gg) {   // prologue only
        float* xs = (float*)(smem + SM_X + (gg & 1) * XBUFB);
        float* km = (float*)(smem + SM_KM + (gg & 1) * 448);
#pragma unroll
        for (int i = 0; i < 4; i++) {
            int id = tid + i * 256;
            if (id < 2 * XSTG) {
                int ch = id >= XSTG, ii = id - ch * XSTG;
                float v = (h0 * 31 + ii < 961) ? xb[(size_t)(gg * 2 + ch) * 961 + h0 * 31 + ii] : 0.f;
                xs[ch * XCH + (ii / 31) * 32 + (ii % 31)] = v;
            }
        }
        if (tid < KG) km[tid] = kern_fetch(gg);
    };

    // ---------- prologue ----------
    cpasync_A(0);
    stage_xk_direct(0);
    stage_xk_direct(1);
    __syncthreads();           // xs/km(0),(1) + rtab visible
    build_B(0);
    CP_WAIT0();                // A(0) in

    float acc[2][10][4];
#pragma unroll
    for (int mi = 0; mi < 2; mi++)
#pragma unroll
        for (int j = 0; j < 10; j++)
#pragma unroll
            for (int q = 0; q < 4; q++) acc[mi][j][q] = 0.f;

    const uint32_t apat = (uint32_t)((mw * 32 + (lid & 15)) * PITCHB + (lid >> 4) * 16);
    const uint32_t bpat = (uint32_t)((nw * 80 + (lid & 7) + ((lid & 16) ? 8 : 0)) * PITCHB
                                     + ((lid & 8) ? 16 : 0));

    // ---------- main loop: ONE sync per group ----------
#pragma unroll 1
    for (int g = 0; g < NGROUP; g++) {
        const int buf = g & 1;
        __syncthreads();   // publishes: B(g), xs/km(g+1), A(g)

        if (g + 1 < NGROUP) cpasync_A(g + 1);

        // prefetch x(g+2)/kern(g+2) into regs
        float xv[4]; float kv = 0.f;
        if (g + 2 < NGROUP) {
#pragma unroll
            for (int i = 0; i < 4; i++) {
                int id = tid + i * 256;
                xv[i] = 0.f;
                if (id < 2 * XSTG) {
                    int ch = id >= XSTG, ii = id - ch * XSTG;
                    if (h0 * 31 + ii < 961)
                        xv[i] = xb[(size_t)((g + 2) * 2 + ch) * 961 + h0 * 31 + ii];
                }
            }
            kv = kern_fetch(g + 2);
        }

        // MMA(g): fp16-accumulate chains of <=2 ksteps, drained into fp32 masters
        {
            const uint32_t ab = sbase + SM_A + buf * A_TILE + apat;
            const uint32_t bb = sbase + SM_B + buf * B_TILE + bpat;
            uint32_t dacc[2][10][2];
#pragma unroll
            for (int k = 0; k < KSTEPS; k++) {
                uint32_t A0[4], A1[4], Bv[20];
                ldsm4(A0, ab + k * 32);
                ldsm4(A1, ab + 3840 + k * 32);
#pragma unroll
                for (int j5 = 0; j5 < 5; j5++) ldsm4(&Bv[j5 * 4], bb + j5 * 3840 + k * 32);
                const bool st = (k == 0) | (k == 2) | (k == 4) | (k == 6);
#pragma unroll
                for (int j = 0; j < 10; j++) {
                    const uint32_t* bf = &Bv[(j >> 1) * 4 + (j & 1) * 2];
                    if (st) {
                        mma_h16z(dacc[0][j], A0, bf);
                        mma_h16z(dacc[1][j], A1, bf);
                    } else {
                        mma_h16a(dacc[0][j], A0, bf);
                        mma_h16a(dacc[1][j], A1, bf);
                    }
                }
                if ((k == 1) | (k == 3) | (k == 5) | (k == 6)) {
#pragma unroll
                    for (int mi = 0; mi < 2; mi++)
#pragma unroll
                        for (int j = 0; j < 10; j++) dq(acc[mi][j], dacc[mi][j]);
                }
            }
        }

        if (g + 1 < NGROUP) build_B((g + 1) & 1);

        // stage x(g+2)/km(g+2) into buf g&1
        if (g + 2 < NGROUP) {
            float* xs = (float*)(smem + SM_X + buf * XBUFB);
            float* km = (float*)(smem + SM_KM + buf * 448);
#pragma unroll
            for (int i = 0; i < 4; i++) {
                int id = tid + i * 256;
                if (id < 2 * XSTG) {
                    int ch = id >= XSTG, ii = id - ch * XSTG;
                    xs[ch * XCH + (ii / 31) * 32 + (ii % 31)] = xv[i];
                }
            }
            if (tid < KG) km[tid] = kv;
        }

        CP_WAIT0();        // A(g+1) arrived
    }

    // ---------- epilogue ----------
    const float s = 1.0f / 256.0f;
#pragma unroll
    for (int mi = 0; mi < 2; mi++) {
        int o = o0 + mw * 32 + mi * 16 + (lid >> 2);
        float bv0 = __ldg(bias + o);
        float bv1 = __ldg(bias + o + 8);
        float* r0 = out + ((size_t)b * O_ + o) * HW;
        float* r1 = r0 + 8 * HW;
#pragma unroll
        for (int j = 0; j < 10; j++) {
            int p = p0 + nw * 80 + j * 8 + 2 * (lid & 3);
            if (p < HW)     r0[p]     = acc[mi][j][0] * s + bv0;
            if (p + 1 < HW) r0[p + 1] = acc[mi][j][1] * s + bv0;
            if (p < HW)     r1[p]     = acc[mi][j][2] * s + bv1;
            if (p + 1 < HW) r1[p + 1] = acc[mi][j][3] * s + bv1;
        }
    }
}

extern "C" void kernel_launch(void* const* d_in, const int* in_sizes, int n_in,
                              void* d_out, int out_size) {
    const float* x      = (const float*)d_in[0];
    const float* kernel = (const float*)d_in[1];
    const float* weight = (const float*)d_in[2];
    const float* bias   = (const float*)d_in[3];
    float* out = (float*)d_out;

    cudaFuncSetAttribute(dwconv_hmma11, cudaFuncAttributeMaxDynamicSharedMemorySize, SMEM_DYN);

    precompute_w<<<15360, 256>>>(weight);
    dwconv_hmma11<<<256, THREADS, SMEM_DYN>>>(x, kernel, bias, out);
}

// round 15
// speedup vs baseline: 1.6402x; 1.6402x over previous
#include <cuda_runtime.h>
#include <cuda_fp16.h>
#include <cstdint>

#define B_  32
#define O_  256
#define KK  49
#define HW  625
#define WO  25
#define CKK 12544

#define THREADS 512          // wid 0-7 consumers (4Mx2N, 32x80), wid 8-15 producers
#define NGROUP  128
#define KG      112          // k = ch*56 + ki*8 + kj (kj<7 real)
#define KSTEPS  7
#define PITCH   120
#define PITCHB  240
#define A_TILE  30720
#define B_TILE  38400

#define XCH     448
#define XSTG    434
#define XBUFB   3584

#define SM_A    0
#define SM_B    61440
#define SM_X    138240
#define SM_KM   145408
#define SM_RTAB 146304
#define SMEM_DYN 147456

__device__ __half g_W[2][NGROUP][128][PITCH];

__device__ __forceinline__ uint32_t smem_u32(const void* p) {
    uint32_t a;
    asm("{ .reg .u64 t; cvta.to.shared.u64 t, %1; cvt.u32.u64 %0, t; }" : "=r"(a) : "l"(p));
    return a;
}
__device__ __forceinline__ void ldsm4(uint32_t* r, uint32_t addr) {
    asm volatile("ldmatrix.sync.aligned.m8n8.x4.shared.b16 {%0,%1,%2,%3}, [%4];"
                 : "=r"(r[0]), "=r"(r[1]), "=r"(r[2]), "=r"(r[3]) : "r"(addr));
}
__device__ __forceinline__ void mma_f16(float* d, const uint32_t* a, const uint32_t* b) {
    asm volatile("mma.sync.aligned.m16n8k16.row.col.f32.f16.f16.f32 "
                 "{%0,%1,%2,%3}, {%4,%5,%6,%7}, {%8,%9}, {%0,%1,%2,%3};"
                 : "+f"(d[0]), "+f"(d[1]), "+f"(d[2]), "+f"(d[3])
                 : "r"(a[0]), "r"(a[1]), "r"(a[2]), "r"(a[3]), "r"(b[0]), "r"(b[1]));
}
#define CP16(dst, src) \
    asm volatile("cp.async.cg.shared.global [%0], [%1], 16;" :: "r"(dst), "l"(src) : "memory")
#define CP_COMMIT() asm volatile("cp.async.commit_group;" ::: "memory")
#define CP_WAIT0()  asm volatile("cp.async.wait_group 0;" ::: "memory")
#define BSYNC(id)   asm volatile("bar.sync %0, 512;"   :: "r"(id) : "memory")
#define BARRIVE(id) asm volatile("bar.arrive %0, 512;" :: "r"(id) : "memory")
#define PSYNC()     asm volatile("bar.sync 5, 256;" ::: "memory")

__global__ void precompute_w(const float* __restrict__ w) {
    long idx = (long)blockIdx.x * 256 + threadIdx.x;
    int k = idx % PITCH;
    int o = (idx / PITCH) & 127;
    int g = (idx / (PITCH * 128)) & 127;
    int t = (int)(idx / ((long)PITCH * 128 * NGROUP));
    if (t >= 2) return;
    float v = 0.f;
    if (k < KG) {
        int ch = k / 56, r = (k % 56) / 8, kj = k & 7;
        if (kj < 7)
            v = w[(size_t)(t * 128 + o) * CKK + (g * 2 + ch) * KK + r * 7 + kj] * 256.f;
    }
    g_W[t][g][o][k] = __float2half_rn(v);
}

__global__ __launch_bounds__(THREADS)
void dwconv_ws(const float* __restrict__ x, const float* __restrict__ kern,
               const float* __restrict__ bias, float* __restrict__ out)
{
    extern __shared__ __align__(128) char smem[];
    const uint32_t sbase = smem_u32(smem);

    const int tid = threadIdx.x, wid = tid >> 5, lid = tid & 31;
    const int blk = blockIdx.x;
    const int pt = blk & 3, t = (blk >> 2) & 1, b = blk >> 3;
    const int p0 = pt * 160, o0 = t * 128;
    const int h0 = p0 / WO;

    int* rtab = (int*)(smem + SM_RTAB);
    if (tid < 160) {
        int pg = p0 + tid;
        rtab[tid] = (pg < HW) ? ((pg / WO) - h0) * 32 + (pg % WO) : -1;
    }
    __syncthreads();

    const float* xb = x    + (size_t)b * 256 * 961;
    const float* kb = kern + (size_t)b * CKK;

    if (wid >= 8) {
        // ======================= PRODUCER warps =======================
        const int ptid = tid - 256;        // 0..255
        const int pwid = wid - 8;          // 0..7

        auto kern_fetch = [&](int gg) -> float {
            if (ptid >= KG) return 0.f;
            int ch = ptid / 56, r = (ptid % 56) / 8, kj = ptid & 7;
            if (kj >= 7) return 0.f;
            return kb[(size_t)(gg * 2 + ch) * KK + r * 7 + kj];
        };
        auto build_B = [&](int s) {
            char* bt = smem + SM_B + s * B_TILE;
            const float* xs = (const float*)(smem + SM_X + s * XBUFB);
            const float* km = (const float*)(smem + SM_KM + s * 448);
#pragma unroll
            for (int it = 0; it < 9; it++) {
                int wt = it * 8 + pwid;    // 70 warp-tasks
                if (wt < 70) {
                    int pg5 = wt / 14;
                    int rem = wt - pg5 * 14;
                    int ch = rem / 7, ki = rem - (rem / 7) * 7;
                    int p = pg5 * 32 + lid;
                    int rb = rtab[p];
                    uint4 val = make_uint4(0, 0, 0, 0);
                    if (rb >= 0) {
                        const float* kp = km + ch * 56 + ki * 8;
                        const float4 ka = *(const float4*)kp;
                        const float4 kc = *(const float4*)(kp + 4);
                        const float* xp = xs + ch * XCH + rb + ki * 32;
                        __half2 h0v = __floats2half2_rn(xp[0] * ka.x, xp[1] * ka.y);
                        __half2 h1v = __floats2half2_rn(xp[2] * ka.z, xp[3] * ka.w);
                        __half2 h2v = __floats2half2_rn(xp[4] * kc.x, xp[5] * kc.y);
                        __half2 h3v = __floats2half2_rn(xp[6] * kc.z, 0.f);
                        val = make_uint4(*(uint32_t*)&h0v, *(uint32_t*)&h1v,
                                         *(uint32_t*)&h2v, *(uint32_t*)&h3v);
                    }
                    *(uint4*)(bt + p * PITCHB + (ch * 7 + ki) * 16) = val;
                }
            }
        };
        auto cpasync_A = [&](int gg) {
            const char* src = (const char*)&g_W[t][gg][0][0];
            uint32_t dst = sbase + SM_A + (gg & 1) * A_TILE;
#pragma unroll
            for (int i = 0; i < 8; i++) {
                int idx = i * 256 + ptid;
                if (idx < 1920) CP16(dst + idx * 16, src + idx * 16);
            }
            CP_COMMIT();
        };
        auto stage_direct = [&](int gg) {   // prologue only: LDG -> STS
            float* xs = (float*)(smem + SM_X + (gg & 1) * XBUFB);
            float* km = (float*)(smem + SM_KM + (gg & 1) * 448);
#pragma unroll
            for (int i = 0; i < 4; i++) {
                int id = ptid + i * 256;
                if (id < 2 * XSTG) {
                    int ch = id >= XSTG, ii = id - ch * XSTG;
                    float v = (h0 * 31 + ii < 961)
                              ? xb[(size_t)(gg * 2 + ch) * 961 + h0 * 31 + ii] : 0.f;
                    xs[ch * XCH + (ii / 31) * 32 + (ii % 31)] = v;
                }
            }
            if (ptid < KG) km[ptid] = kern_fetch(gg);
        };

        // ---- producer prologue ----
        cpasync_A(0);
        stage_direct(0);
        stage_direct(1);
        PSYNC();                       // xs(0)/xs(1)/km visible to all producers
        build_B(0);
        // prefetch x(2)/km(2) into regs
        float xv[4]; float kv = 0.f;
#pragma unroll
        for (int i = 0; i < 4; i++) {
            int id = ptid + i * 256;
            xv[i] = 0.f;
            if (id < 2 * XSTG) {
                int ch = id >= XSTG, ii = id - ch * XSTG;
                if (h0 * 31 + ii < 961) xv[i] = xb[(size_t)(4 + ch) * 961 + h0 * 31 + ii];
            }
        }
        kv = kern_fetch(2);
        CP_WAIT0();                    // A(0) in
        __threadfence_block();
        BARRIVE(1);                    // ready(0) (parity 0)

        // ---- producer main loop: build B(g+1) during consumer MMA(g) ----
#pragma unroll 1
        for (int g = 0; g < NGROUP - 1; g++) {
            const int nb = (g + 1) & 1;
            BSYNC(3 + nb);             // consumed: B/A buf nb free
            cpasync_A(g + 1);
            build_B(nb);               // B(g+1) from xs[nb]/km[nb]
            // stage x(g+2)/km(g+2) from regs into buf g&1
            if (g + 2 < NGROUP) {
                float* xs = (float*)(smem + SM_X + (g & 1) * XBUFB);
                float* km = (float*)(smem + SM_KM + (g & 1) * 448);
#pragma unroll
                for (int i = 0; i < 4; i++) {
                    int id = ptid + i * 256;
                    if (id < 2 * XSTG) {
                        int ch = id >= XSTG, ii = id - ch * XSTG;
                        xs[ch * XCH + (ii / 31) * 32 + (ii % 31)] = xv[i];
                    }
                }
                if (ptid < KG) km[ptid] = kv;
            }
            // prefetch x(g+3)/km(g+3) into regs
            if (g + 3 < NGROUP) {
#pragma unroll
                for (int i = 0; i < 4; i++) {
                    int id = ptid + i * 256;
                    xv[i] = 0.f;
                    if (id < 2 * XSTG) {
                        int ch = id >= XSTG, ii = id - ch * XSTG;
                        if (h0 * 31 + ii < 961)
                            xv[i] = xb[(size_t)((g + 3) * 2 + ch) * 961 + h0 * 31 + ii];
                    }
                }
                kv = kern_fetch(g + 3);
            }
            CP_WAIT0();                // A(g+1) landed
            __threadfence_block();
            BARRIVE(1 + nb);           // ready(g+1)
        }
    } else {
        // ======================= CONSUMER warps =======================
        const int mw = wid >> 1, nw = wid & 1;

        float acc[2][10][4];
#pragma unroll
        for (int mi = 0; mi < 2; mi++)
#pragma unroll
            for (int j = 0; j < 10; j++)
#pragma unroll
                for (int q = 0; q < 4; q++) acc[mi][j][q] = 0.f;

        const uint32_t apat = (uint32_t)((mw * 32 + (lid & 15)) * PITCHB + (lid >> 4) * 16);
        const uint32_t bpat = (uint32_t)((nw * 80 + (lid & 7) + ((lid & 16) ? 8 : 0)) * PITCHB
                                         + ((lid & 8) ? 16 : 0));

        BARRIVE(4);                    // prime cons_odd (frees producer g=0)

#pragma unroll 1
        for (int g = 0; g < NGROUP; g++) {
            const int buf = g & 1;
            BSYNC(1 + buf);            // ready(g)
            const uint32_t ab = sbase + SM_A + buf * A_TILE + apat;
            const uint32_t bb = sbase + SM_B + buf * B_TILE + bpat;
#pragma unroll
            for (int k = 0; k < KSTEPS; k++) {
                uint32_t A0[4], A1[4], Bv[20];
                ldsm4(A0, ab + k * 32);
                ldsm4(A1, ab + 3840 + k * 32);
#pragma unroll
                for (int j5 = 0; j5 < 5; j5++) ldsm4(&Bv[j5 * 4], bb + j5 * 3840 + k * 32);
#pragma unroll
                for (int j = 0; j < 10; j++) {
                    const uint32_t* bf = &Bv[(j >> 1) * 4 + (j & 1) * 2];
                    mma_f16(acc[0][j], A0, bf);
                    mma_f16(acc[1][j], A1, bf);
                }
            }
            BARRIVE(3 + buf);          // consumed(g)
        }

        // ---- epilogue (consumers only) ----
        const float s = 1.0f / 256.0f;
#pragma unroll
        for (int mi = 0; mi < 2; mi++) {
            int o = o0 + mw * 32 + mi * 16 + (lid >> 2);
            float bv0 = __ldg(bias + o);
            float bv1 = __ldg(bias + o + 8);
            float* r0 = out + ((size_t)b * O_ + o) * HW;
            float* r1 = r0 + 8 * HW;
#pragma unroll
            for (int j = 0; j < 10; j++) {
                int p = p0 + nw * 80 + j * 8 + 2 * (lid & 3);
                if (p < HW)     r0[p]     = acc[mi][j][0] * s + bv0;
                if (p + 1 < HW) r0[p + 1] = acc[mi][j][1] * s + bv0;
                if (p < HW)     r1[p]     = acc[mi][j][2] * s + bv1;
                if (p + 1 < HW) r1[p + 1] = acc[mi][j][3] * s + bv1;
            }
        }
    }
}

extern "C" void kernel_launch(void* const* d_in, const int* in_sizes, int n_in,
                              void* d_out, int out_size) {
    const float* x      = (const float*)d_in[0];
    const float* kernel = (const float*)d_in[1];
    const float* weight = (const float*)d_in[2];
    const float* bias   = (const float*)d_in[3];
    float* out = (float*)d_out;

    cudaFuncSetAttribute(dwconv_ws, cudaFuncAttributeMaxDynamicSharedMemorySize, SMEM_DYN);

    precompute_w<<<15360, 256>>>(weight);
    dwconv_ws<<<256, THREADS, SMEM_DYN>>>(x, kernel, bias, out);
}

// round 16
// speedup vs baseline: 1.6481x; 1.0048x over previous
#include <cuda_runtime.h>
#include <cuda_fp16.h>
#include <cstdint>

#define B_  32
#define O_  256
#define KK  49
#define HW  625
#define WO  25
#define CKK 12544

#define THREADS 512          // wid 0-7 consumers (2Mx4N, 64x40), wid 8-15 producers
#define NGROUP  128
#define KG      112
#define KSTEPS  7
#define PITCH   120
#define PITCHB  240
#define A_TILE  30720
#define B_TILE  38400

#define XCH     448
#define XSTG    434
#define XBUFB   3584

#define SM_A    0            // 3 * 30720 = 92160
#define SM_B    92160        // 3 * 38400 -> 207360
#define SM_X    207360       // 3 * 3584  -> 218112
#define SM_KM   218112       // 3 * 448   -> 219456
#define SM_RTAB 219456       // 160 ints  -> 220096
#define SMEM_DYN 220160

__device__ __half g_W[2][NGROUP][128][PITCH];

__device__ __forceinline__ uint32_t smem_u32(const void* p) {
    uint32_t a;
    asm("{ .reg .u64 t; cvta.to.shared.u64 t, %1; cvt.u32.u64 %0, t; }" : "=r"(a) : "l"(p));
    return a;
}
__device__ __forceinline__ void ldsm4(uint32_t* r, uint32_t addr) {
    asm volatile("ldmatrix.sync.aligned.m8n8.x4.shared.b16 {%0,%1,%2,%3}, [%4];"
                 : "=r"(r[0]), "=r"(r[1]), "=r"(r[2]), "=r"(r[3]) : "r"(addr));
}
__device__ __forceinline__ void ldsm2(uint32_t* r, uint32_t addr) {
    asm volatile("ldmatrix.sync.aligned.m8n8.x2.shared.b16 {%0,%1}, [%2];"
                 : "=r"(r[0]), "=r"(r[1]) : "r"(addr));
}
__device__ __forceinline__ void mma_f16(float* d, const uint32_t* a, const uint32_t* b) {
    asm volatile("mma.sync.aligned.m16n8k16.row.col.f32.f16.f16.f32 "
                 "{%0,%1,%2,%3}, {%4,%5,%6,%7}, {%8,%9}, {%0,%1,%2,%3};"
                 : "+f"(d[0]), "+f"(d[1]), "+f"(d[2]), "+f"(d[3])
                 : "r"(a[0]), "r"(a[1]), "r"(a[2]), "r"(a[3]), "r"(b[0]), "r"(b[1]));
}
#define CP16(dst, src) \
    asm volatile("cp.async.cg.shared.global [%0], [%1], 16;" :: "r"(dst), "l"(src) : "memory")
#define CP_COMMIT() asm volatile("cp.async.commit_group;" ::: "memory")
#define CP_WAIT0()  asm volatile("cp.async.wait_group 0;" ::: "memory")
#define BSYNC(id)   asm volatile("bar.sync %0, 512;"   :: "r"(id) : "memory")
#define BARRIVE(id) asm volatile("bar.arrive %0, 512;" :: "r"(id) : "memory")
#define PSYNC()     asm volatile("bar.sync 7, 256;" ::: "memory")

__global__ void precompute_w(const float* __restrict__ w) {
    long idx = (long)blockIdx.x * 256 + threadIdx.x;
    int k = idx % PITCH;
    int o = (idx / PITCH) & 127;
    int g = (idx / (PITCH * 128)) & 127;
    int t = (int)(idx / ((long)PITCH * 128 * NGROUP));
    if (t >= 2) return;
    float v = 0.f;
    if (k < KG) {
        int ch = k / 56, r = (k % 56) / 8, kj = k & 7;
        if (kj < 7)
            v = w[(size_t)(t * 128 + o) * CKK + (g * 2 + ch) * KK + r * 7 + kj] * 256.f;
    }
    g_W[t][g][o][k] = __float2half_rn(v);
}

__global__ __launch_bounds__(THREADS)
void dwconv_ws3(const float* __restrict__ x, const float* __restrict__ kern,
                const float* __restrict__ bias, float* __restrict__ out)
{
    extern __shared__ __align__(128) char smem[];
    const uint32_t sbase = smem_u32(smem);

    const int tid = threadIdx.x, wid = tid >> 5, lid = tid & 31;
    const int blk = blockIdx.x;
    const int pt = blk & 3, t = (blk >> 2) & 1, b = blk >> 3;
    const int p0 = pt * 160, o0 = t * 128;
    const int h0 = p0 / WO;

    int* rtab = (int*)(smem + SM_RTAB);
    if (tid < 160) {
        int pg = p0 + tid;
        rtab[tid] = (pg < HW) ? ((pg / WO) - h0) * 32 + (pg % WO) : -1;
    }
    __syncthreads();

    const float* xb = x    + (size_t)b * 256 * 961;
    const float* kb = kern + (size_t)b * CKK;

    if (wid >= 8) {
        // ======================= PRODUCER warps =======================
        const int ptid = tid - 256;
        const int pwid = wid - 8;

        auto kern_fetch = [&](int gg) -> float {
            if (ptid >= KG) return 0.f;
            int ch = ptid / 56, r = (ptid % 56) / 8, kj = ptid & 7;
            if (kj >= 7) return 0.f;
            return kb[(size_t)(gg * 2 + ch) * KK + r * 7 + kj];
        };
        auto build_B = [&](int s) {
            char* bt = smem + SM_B + s * B_TILE;
            const float* xs = (const float*)(smem + SM_X + s * XBUFB);
            const float* km = (const float*)(smem + SM_KM + s * 448);
#pragma unroll
            for (int it = 0; it < 9; it++) {
                int wt = it * 8 + pwid;    // 70 warp-tasks
                if (wt < 70) {
                    int pg5 = wt / 14;
                    int rem = wt - pg5 * 14;
                    int ch = rem / 7, ki = rem - (rem / 7) * 7;
                    int p = pg5 * 32 + lid;
                    int rb = rtab[p];
                    uint4 val = make_uint4(0, 0, 0, 0);
                    if (rb >= 0) {
                        const float* kp = km + ch * 56 + ki * 8;
                        const float4 ka = *(const float4*)kp;
                        const float4 kc = *(const float4*)(kp + 4);
                        const float* xp = xs + ch * XCH + rb + ki * 32;
                        __half2 h0v = __floats2half2_rn(xp[0] * ka.x, xp[1] * ka.y);
                        __half2 h1v = __floats2half2_rn(xp[2] * ka.z, xp[3] * ka.w);
                        __half2 h2v = __floats2half2_rn(xp[4] * kc.x, xp[5] * kc.y);
                        __half2 h3v = __floats2half2_rn(xp[6] * kc.z, 0.f);
                        val = make_uint4(*(uint32_t*)&h0v, *(uint32_t*)&h1v,
                                         *(uint32_t*)&h2v, *(uint32_t*)&h3v);
                    }
                    *(uint4*)(bt + p * PITCHB + (ch * 7 + ki) * 16) = val;
                }
            }
        };
        auto cpasync_A = [&](int gg, int s) {
            const char* src = (const char*)&g_W[t][gg][0][0];
            uint32_t dst = sbase + SM_A + s * A_TILE;
#pragma unroll
            for (int i = 0; i < 8; i++) {
                int idx = i * 256 + ptid;
                if (idx < 1920) CP16(dst + idx * 16, src + idx * 16);
            }
            CP_COMMIT();
        };
        auto stage_direct = [&](int gg, int s) {   // prologue only
            float* xs = (float*)(smem + SM_X + s * XBUFB);
            float* km = (float*)(smem + SM_KM + s * 448);
#pragma unroll
            for (int i = 0; i < 4; i++) {
                int id = ptid + i * 256;
                if (id < 2 * XSTG) {
                    int ch = id >= XSTG, ii = id - ch * XSTG;
                    float v = (h0 * 31 + ii < 961)
                              ? xb[(size_t)(gg * 2 + ch) * 961 + h0 * 31 + ii] : 0.f;
                    xs[ch * XCH + (ii / 31) * 32 + (ii % 31)] = v;
                }
            }
            if (ptid < KG) km[ptid] = kern_fetch(gg);
        };

        // ---- producer prologue: xs/km(0),(1); prefetch x(2) ----
        stage_direct(0, 0);
        stage_direct(1, 1);
        PSYNC();
        float xv[4]; float kv;
#pragma unroll
        for (int i = 0; i < 4; i++) {
            int id = ptid + i * 256;
            xv[i] = 0.f;
            if (id < 2 * XSTG) {
                int ch = id >= XSTG, ii = id - ch * XSTG;
                if (h0 * 31 + ii < 961) xv[i] = xb[(size_t)(4 + ch) * 961 + h0 * 31 + ii];
            }
        }
        kv = kern_fetch(2);

        // ---- producer main loop: produce (A,B)(g) into slot g%3 ----
        int sl = 0;
#pragma unroll 1
        for (int g = 0; g < NGROUP; g++) {
            BSYNC(4 + sl);             // slot sl free (consumed g-3 / pre-armed)
            cpasync_A(g, sl);
            build_B(sl);               // from xs/km slot sl (staged at iter g-2)
            // stage xs/km(g+2) into slot (g+2)%3
            if (g + 2 < NGROUP) {
                int s2 = sl + 2; if (s2 >= 3) s2 -= 3;
                float* xs = (float*)(smem + SM_X + s2 * XBUFB);
                float* km = (float*)(smem + SM_KM + s2 * 448);
#pragma unroll
                for (int i = 0; i < 4; i++) {
                    int id = ptid + i * 256;
                    if (id < 2 * XSTG) {
                        int ch = id >= XSTG, ii = id - ch * XSTG;
                        xs[ch * XCH + (ii / 31) * 32 + (ii % 31)] = xv[i];
                    }
                }
                if (ptid < KG) km[ptid] = kv;
            }
            // prefetch x(g+3)/kern(g+3)
            if (g + 3 < NGROUP) {
#pragma unroll
                for (int i = 0; i < 4; i++) {
                    int id = ptid + i * 256;
                    xv[i] = 0.f;
                    if (id < 2 * XSTG) {
                        int ch = id >= XSTG, ii = id - ch * XSTG;
                        if (h0 * 31 + ii < 961)
                            xv[i] = xb[(size_t)((g + 3) * 2 + ch) * 961 + h0 * 31 + ii];
                    }
                }
                kv = kern_fetch(g + 3);
            }
            CP_WAIT0();
            __threadfence_block();
            BARRIVE(1 + sl);           // ready(g)
            sl = (sl == 2) ? 0 : sl + 1;
        }
    } else {
        // ======================= CONSUMER warps =======================
        const int mw = wid >> 2, nw = wid & 3;   // 2(M) x 4(N), warp tile 64 x 40

        float acc[4][5][4];
#pragma unroll
        for (int mi = 0; mi < 4; mi++)
#pragma unroll
            for (int j = 0; j < 5; j++)
#pragma unroll
                for (int q = 0; q < 4; q++) acc[mi][j][q] = 0.f;

        const uint32_t apat = (uint32_t)((mw * 64 + (lid & 15)) * PITCHB + (lid >> 4) * 16);
        const uint32_t bpat = (uint32_t)((nw * 40 + (lid & 7) + ((lid & 16) ? 8 : 0)) * PITCHB
                                         + ((lid & 8) ? 16 : 0));
        const int l2 = lid & 15;
        const uint32_t bpat2 = (uint32_t)((nw * 40 + 32 + (l2 & 7)) * PITCHB
                                          + ((l2 & 8) ? 16 : 0));

        BARRIVE(4); BARRIVE(5); BARRIVE(6);   // pre-arm all three slots

        int sl = 0;
#pragma unroll 1
        for (int g = 0; g < NGROUP; g++) {
            BSYNC(1 + sl);             // ready(g)
            const uint32_t ab = sbase + SM_A + sl * A_TILE + apat;
            const uint32_t bb = sbase + SM_B + sl * B_TILE;
#pragma unroll
            for (int k = 0; k < KSTEPS; k++) {
                uint32_t Af[4][4], Bv[10];
#pragma unroll
                for (int mi = 0; mi < 4; mi++) ldsm4(Af[mi], ab + mi * 3840 + k * 32);
                ldsm4(&Bv[0], bb + bpat + k * 32);
                ldsm4(&Bv[4], bb + bpat + 3840 + k * 32);
                ldsm2(&Bv[8], bb + bpat2 + k * 32);
#pragma unroll
                for (int j = 0; j < 5; j++) {
                    const uint32_t* bf = &Bv[j * 2];
#pragma unroll
                    for (int mi = 0; mi < 4; mi++) mma_f16(acc[mi][j], Af[mi], bf);
                }
            }
            BARRIVE(4 + sl);           // consumed(g)
            sl = (sl == 2) ? 0 : sl + 1;
        }

        // ---- epilogue ----
        const float s = 1.0f / 256.0f;
#pragma unroll
        for (int mi = 0; mi < 4; mi++) {
            int o = o0 + mw * 64 + mi * 16 + (lid >> 2);
            float bv0 = __ldg(bias + o);
            float bv1 = __ldg(bias + o + 8);
            float* r0 = out + ((size_t)b * O_ + o) * HW;
            float* r1 = r0 + 8 * HW;
#pragma unroll
            for (int j = 0; j < 5; j++) {
                int p = p0 + nw * 40 + j * 8 + 2 * (lid & 3);
                if (p < HW)     r0[p]     = acc[mi][j][0] * s + bv0;
                if (p + 1 < HW) r0[p + 1] = acc[mi][j][1] * s + bv0;
                if (p < HW)     r1[p]     = acc[mi][j][2] * s + bv1;
                if (p + 1 < HW) r1[p + 1] = acc[mi][j][3] * s + bv1;
            }
        }
    }
}

extern "C" void kernel_launch(void* const* d_in, const int* in_sizes, int n_in,
                              void* d_out, int out_size) {
    const float* x      = (const float*)d_in[0];
    const float* kernel = (const float*)d_in[1];
    const float* weight = (const float*)d_in[2];
    const float* bias   = (const float*)d_in[3];
    float* out = (float*)d_out;

    cudaFuncSetAttribute(dwconv_ws3, cudaFuncAttributeMaxDynamicSharedMemorySize, SMEM_DYN);

    precompute_w<<<15360, 256>>>(weight);
    dwconv_ws3<<<256, THREADS, SMEM_DYN>>>(x, kernel, bias, out);
}

// round 17
// speedup vs baseline: 1.8233x; 1.1063x over previous
#include <cuda_runtime.h>
#include <cuda_fp16.h>
#include <cstdint>

#define B_  32
#define O_  256
#define KK  49
#define HW  625
#define WO  25
#define CKK 12544

#define THREADS 512          // wid 0-7 consumers (2Mx4N, 64x40), wid 8-15 producers
#define NGROUP  128
#define KG      112
#define KSTEPS  7
#define PITCH   120
#define PITCHB  240
#define A_TILE  30720
#define B_TILE  38400

#define XCH     448          // halves per channel slab (14 rows * 32)
#define XSTG    434
#define XBUFB   2048         // 2ch * 448 halves * 2B = 1792, padded

#define SM_A    0            // 3 * 30720 = 92160
#define SM_B    92160        // 3 * 38400 -> 207360
#define SM_X    207360       // 3 * 2048  -> 213504
#define SM_KM   213504       // 3 * 448   -> 214848
#define SM_RTAB 214848       // 160 ints  -> 215488
#define SMEM_DYN 215552

__device__ __half g_W[2][NGROUP][128][PITCH];

__device__ __forceinline__ uint32_t smem_u32(const void* p) {
    uint32_t a;
    asm("{ .reg .u64 t; cvta.to.shared.u64 t, %1; cvt.u32.u64 %0, t; }" : "=r"(a) : "l"(p));
    return a;
}
__device__ __forceinline__ void ldsm4(uint32_t* r, uint32_t addr) {
    asm volatile("ldmatrix.sync.aligned.m8n8.x4.shared.b16 {%0,%1,%2,%3}, [%4];"
                 : "=r"(r[0]), "=r"(r[1]), "=r"(r[2]), "=r"(r[3]) : "r"(addr));
}
__device__ __forceinline__ void ldsm2(uint32_t* r, uint32_t addr) {
    asm volatile("ldmatrix.sync.aligned.m8n8.x2.shared.b16 {%0,%1}, [%2];"
                 : "=r"(r[0]), "=r"(r[1]) : "r"(addr));
}
__device__ __forceinline__ void mma_f16(float* d, const uint32_t* a, const uint32_t* b) {
    asm volatile("mma.sync.aligned.m16n8k16.row.col.f32.f16.f16.f32 "
                 "{%0,%1,%2,%3}, {%4,%5,%6,%7}, {%8,%9}, {%0,%1,%2,%3};"
                 : "+f"(d[0]), "+f"(d[1]), "+f"(d[2]), "+f"(d[3])
                 : "r"(a[0]), "r"(a[1]), "r"(a[2]), "r"(a[3]), "r"(b[0]), "r"(b[1]));
}
#define CP16(dst, src) \
    asm volatile("cp.async.cg.shared.global [%0], [%1], 16;" :: "r"(dst), "l"(src) : "memory")
#define CP_COMMIT() asm volatile("cp.async.commit_group;" ::: "memory")
#define CP_WAIT0()  asm volatile("cp.async.wait_group 0;" ::: "memory")
#define BSYNC(id)   asm volatile("bar.sync %0, 512;"   :: "r"(id) : "memory")
#define BARRIVE(id) asm volatile("bar.arrive %0, 512;" :: "r"(id) : "memory")
#define PSYNC()     asm volatile("bar.sync 7, 256;" ::: "memory")

__global__ void precompute_w(const float* __restrict__ w) {
    long idx = (long)blockIdx.x * 256 + threadIdx.x;
    int k = idx % PITCH;
    int o = (idx / PITCH) & 127;
    int g = (idx / (PITCH * 128)) & 127;
    int t = (int)(idx / ((long)PITCH * 128 * NGROUP));
    if (t >= 2) return;
    float v = 0.f;
    if (k < KG) {
        int ch = k / 56, r = (k % 56) / 8, kj = k & 7;
        if (kj < 7)
            v = w[(size_t)(t * 128 + o) * CKK + (g * 2 + ch) * KK + r * 7 + kj] * 256.f;
    }
    g_W[t][g][o][k] = __float2half_rn(v);
}

__global__ __launch_bounds__(THREADS)
void dwconv_ws4(const float* __restrict__ x, const float* __restrict__ kern,
                const float* __restrict__ bias, float* __restrict__ out)
{
    extern __shared__ __align__(128) char smem[];
    const uint32_t sbase = smem_u32(smem);

    const int tid = threadIdx.x, wid = tid >> 5, lid = tid & 31;
    const int blk = blockIdx.x;
    const int pt = blk & 3, t = (blk >> 2) & 1, b = blk >> 3;
    const int p0 = pt * 160, o0 = t * 128;
    const int h0 = p0 / WO;

    int* rtab = (int*)(smem + SM_RTAB);
    if (tid < 160) {
        int pg = p0 + tid;
        rtab[tid] = (pg < HW) ? ((pg / WO) - h0) * 32 + (pg % WO) : -1;
    }
    __syncthreads();

    const float* xb = x    + (size_t)b * 256 * 961;
    const float* kb = kern + (size_t)b * CKK;

    if (wid >= 8) {
        // ======================= PRODUCER warps =======================
        const int ptid = tid - 256;
        const int pwid = wid - 8;

        auto kern_fetch = [&](int gg) -> float {
            if (ptid >= KG) return 0.f;
            int ch = ptid / 56, r = (ptid % 56) / 8, kj = ptid & 7;
            if (kj >= 7) return 0.f;
            return kb[(size_t)(gg * 2 + ch) * KK + r * 7 + kj];
        };
        auto build_B = [&](int s) {
            char* bt = smem + SM_B + s * B_TILE;
            const __half* xs = (const __half*)(smem + SM_X + s * XBUFB);
            const float*  km = (const float*)(smem + SM_KM + s * 448);
#pragma unroll
            for (int it = 0; it < 9; it++) {
                int wt = it * 8 + pwid;    // 70 warp-tasks: 5 p-grp x 2 ch x 7 ki
                if (wt < 70) {
                    int pg5 = wt / 14;
                    int rem = wt - pg5 * 14;
                    int ch = rem / 7, ki = rem - (rem / 7) * 7;
                    int p = pg5 * 32 + lid;
                    int rb = rtab[p];
                    uint4 val = make_uint4(0, 0, 0, 0);
                    if (rb >= 0) {
                        const float* kp = km + ch * 56 + ki * 8;
                        const float4 ka = *(const float4*)kp;
                        const float4 kc = *(const float4*)(kp + 4);
                        const __half* xp = xs + ch * XCH + rb + ki * 32;
                        float x0 = __half2float(xp[0]);
                        float x1 = __half2float(xp[1]);
                        float x2 = __half2float(xp[2]);
                        float x3 = __half2float(xp[3]);
                        float x4 = __half2float(xp[4]);
                        float x5 = __half2float(xp[5]);
                        float x6 = __half2float(xp[6]);
                        __half2 h0v = __floats2half2_rn(x0 * ka.x, x1 * ka.y);
                        __half2 h1v = __floats2half2_rn(x2 * ka.z, x3 * ka.w);
                        __half2 h2v = __floats2half2_rn(x4 * kc.x, x5 * kc.y);
                        __half2 h3v = __floats2half2_rn(x6 * kc.z, 0.f);
                        val = make_uint4(*(uint32_t*)&h0v, *(uint32_t*)&h1v,
                                         *(uint32_t*)&h2v, *(uint32_t*)&h3v);
                    }
                    *(uint4*)(bt + p * PITCHB + (ch * 7 + ki) * 16) = val;
                }
            }
        };
        auto cpasync_A = [&](int gg, int s) {
            const char* src = (const char*)&g_W[t][gg][0][0];
            uint32_t dst = sbase + SM_A + s * A_TILE;
#pragma unroll
            for (int i = 0; i < 8; i++) {
                int idx = i * 256 + ptid;
                if (idx < 1920) CP16(dst + idx * 16, src + idx * 16);
            }
            CP_COMMIT();
        };
        auto stage_direct = [&](int gg, int s) {   // prologue only
            __half* xs = (__half*)(smem + SM_X + s * XBUFB);
            float*  km = (float*)(smem + SM_KM + s * 448);
#pragma unroll
            for (int i = 0; i < 4; i++) {
                int id = ptid + i * 256;
                if (id < 2 * XSTG) {
                    int ch = id >= XSTG, ii = id - ch * XSTG;
                    float v = (h0 * 31 + ii < 961)
                              ? xb[(size_t)(gg * 2 + ch) * 961 + h0 * 31 + ii] : 0.f;
                    xs[ch * XCH + (ii / 31) * 32 + (ii % 31)] = __float2half_rn(v);
                }
            }
            if (ptid < KG) km[ptid] = kern_fetch(gg);
        };

        // ---- producer prologue: xs/km(0),(1); prefetch x(2) ----
        stage_direct(0, 0);
        stage_direct(1, 1);
        PSYNC();
        float xv[4]; float kv;
#pragma unroll
        for (int i = 0; i < 4; i++) {
            int id = ptid + i * 256;
            xv[i] = 0.f;
            if (id < 2 * XSTG) {
                int ch = id >= XSTG, ii = id - ch * XSTG;
                if (h0 * 31 + ii < 961) xv[i] = xb[(size_t)(4 + ch) * 961 + h0 * 31 + ii];
            }
        }
        kv = kern_fetch(2);

        // ---- producer main loop: produce (A,B)(g) into slot g%3 ----
        int sl = 0;
#pragma unroll 1
        for (int g = 0; g < NGROUP; g++) {
            BSYNC(4 + sl);             // slot sl free
            cpasync_A(g, sl);
            build_B(sl);
            // stage xs/km(g+2) into slot (g+2)%3
            if (g + 2 < NGROUP) {
                int s2 = sl + 2; if (s2 >= 3) s2 -= 3;
                __half* xs = (__half*)(smem + SM_X + s2 * XBUFB);
                float*  km = (float*)(smem + SM_KM + s2 * 448);
#pragma unroll
                for (int i = 0; i < 4; i++) {
                    int id = ptid + i * 256;
                    if (id < 2 * XSTG) {
                        int ch = id >= XSTG, ii = id - ch * XSTG;
                        xs[ch * XCH + (ii / 31) * 32 + (ii % 31)] = __float2half_rn(xv[i]);
                    }
                }
                if (ptid < KG) km[ptid] = kv;
            }
            // prefetch x(g+3)/kern(g+3)
            if (g + 3 < NGROUP) {
#pragma unroll
                for (int i = 0; i < 4; i++) {
                    int id = ptid + i * 256;
                    xv[i] = 0.f;
                    if (id < 2 * XSTG) {
                        int ch = id >= XSTG, ii = id - ch * XSTG;
                        if (h0 * 31 + ii < 961)
                            xv[i] = xb[(size_t)((g + 3) * 2 + ch) * 961 + h0 * 31 + ii];
                    }
                }
                kv = kern_fetch(g + 3);
            }
            CP_WAIT0();
            __threadfence_block();
            BARRIVE(1 + sl);           // ready(g)
            sl = (sl == 2) ? 0 : sl + 1;
        }
    } else {
        // ======================= CONSUMER warps =======================
        const int mw = wid >> 2, nw = wid & 3;   // 2(M) x 4(N), warp tile 64 x 40

        float acc[4][5][4];
#pragma unroll
        for (int mi = 0; mi < 4; mi++)
#pragma unroll
            for (int j = 0; j < 5; j++)
#pragma unroll
                for (int q = 0; q < 4; q++) acc[mi][j][q] = 0.f;

        const uint32_t apat = (uint32_t)((mw * 64 + (lid & 15)) * PITCHB + (lid >> 4) * 16);
        const uint32_t bpat = (uint32_t)((nw * 40 + (lid & 7) + ((lid & 16) ? 8 : 0)) * PITCHB
                                         + ((lid & 8) ? 16 : 0));
        const int l2 = lid & 15;
        const uint32_t bpat2 = (uint32_t)((nw * 40 + 32 + (l2 & 7)) * PITCHB
                                          + ((l2 & 8) ? 16 : 0));

        BARRIVE(4); BARRIVE(5); BARRIVE(6);   // pre-arm all three slots

        int sl = 0;
#pragma unroll 1
        for (int g = 0; g < NGROUP; g++) {
            BSYNC(1 + sl);             // ready(g)
            const uint32_t ab = sbase + SM_A + sl * A_TILE + apat;
            const uint32_t bb = sbase + SM_B + sl * B_TILE;
#pragma unroll
            for (int k = 0; k < KSTEPS; k++) {
                uint32_t Af[4][4], Bv[10];
#pragma unroll
                for (int mi = 0; mi < 4; mi++) ldsm4(Af[mi], ab + mi * 3840 + k * 32);
                ldsm4(&Bv[0], bb + bpat + k * 32);
                ldsm4(&Bv[4], bb + bpat + 3840 + k * 32);
                ldsm2(&Bv[8], bb + bpat2 + k * 32);
#pragma unroll
                for (int j = 0; j < 5; j++) {
                    const uint32_t* bf = &Bv[j * 2];
#pragma unroll
                    for (int mi = 0; mi < 4; mi++) mma_f16(acc[mi][j], Af[mi], bf);
                }
            }
            BARRIVE(4 + sl);           // consumed(g)
            sl = (sl == 2) ? 0 : sl + 1;
        }

        // ---- epilogue ----
        const float s = 1.0f / 256.0f;
#pragma unroll
        for (int mi = 0; mi < 4; mi++) {
            int o = o0 + mw * 64 + mi * 16 + (lid >> 2);
            float bv0 = __ldg(bias + o);
            float bv1 = __ldg(bias + o + 8);
            float* r0 = out + ((size_t)b * O_ + o) * HW;
            float* r1 = r0 + 8 * HW;
#pragma unroll
            for (int j = 0; j < 5; j++) {
                int p = p0 + nw * 40 + j * 8 + 2 * (lid & 3);
                if (p < HW)     r0[p]     = acc[mi][j][0] * s + bv0;
                if (p + 1 < HW) r0[p + 1] = acc[mi][j][1] * s + bv0;
                if (p < HW)     r1[p]     = acc[mi][j][2] * s + bv1;
                if (p + 1 < HW) r1[p + 1] = acc[mi][j][3] * s + bv1;
            }
        }
    }
}

extern "C" void kernel_launch(void* const* d_in, const int* in_sizes, int n_in,
                              void* d_out, int out_size) {
    const float* x      = (const float*)d_in[0];
    const float* kernel = (const float*)d_in[1];
    const float* weight = (const float*)d_in[2];
    const float* bias   = (const float*)d_in[3];
    float* out = (float*)d_out;

    cudaFuncSetAttribute(dwconv_ws4, cudaFuncAttributeMaxDynamicSharedMemorySize, SMEM_DYN);

    precompute_w<<<15360, 256>>>(weight);
    dwconv_ws4<<<256, THREADS, SMEM_DYN>>>(x, kernel, bias, out);
}